// round 17
// baseline (speedup 1.0000x reference)
#include <cuda_runtime.h>
#include <cuda_fp16.h>
#include <math.h>
#include <stdint.h>

// ContinuousRelativePositionalBias — Round 17: R16 structure (all 3 layers on
// tensor cores, 3 CTAs/SM, N-outer) with issue-slot diet:
//  * half2 relu/bias math (pack first, then HMAX2/HADD2 on the idle fma pipe)
//  * b2 pre-packed half2 in smem
//  * direct STG epilogue from ovC lanes (red buffer deleted; 1 barrier stays
//    for the bias double-buffer handoff)

#define ID 512
#define JD 512
#define DD 128
#define MROWS 128
#define NTHREADS 128
#define GRIDSZ 444           // 3 x 148
#define NTILES 8192

#define SWZ(row, chunk) ((unsigned)(row) * 256u + ((((unsigned)(chunk)) ^ ((unsigned)(row) & 7u)) << 4))

// smem byte offsets
#define OFF_W2    0          // 32KB fp16 W2^T [n][k] swizzled
#define OFF_W3T   32768      // 4KB: 16 rows (o, padded) x 128 k (e) fp16, swizzled
#define OFF_BIAS  36864      // 2 x 128 float4 (dbl-buffered)
#define OFF_B2H   40960      // 128 half (64 words), packed pairs
#define OFF_B3    41216      // 4 floats
#define SMEM_BYTES 41232

__device__ __align__(16) uint8_t g_w2h[32768];

__global__ void prep_w2(const float* __restrict__ W2) {
    int idx = blockIdx.x * blockDim.x + threadIdx.x;
    if (idx >= DD * DD) return;
    int n = idx >> 7, k = idx & 127;
    unsigned byte = SWZ(n, k >> 3) + (unsigned)(k & 7) * 2u;
    *(uint16_t*)(g_w2h + byte) = __half_as_ushort(__float2half_rn(W2[k * DD + n]));
}

__device__ __forceinline__ uint32_t smem_u32(const void* p) {
    uint32_t a;
    asm("{ .reg .u64 t; cvta.to.shared.u64 t, %1; cvt.u32.u64 %0, t; }" : "=r"(a) : "l"(p));
    return a;
}
__device__ __forceinline__ void ldsm_x4(uint32_t* r, uint32_t addr) {
    asm volatile("ldmatrix.sync.aligned.m8n8.x4.shared.b16 {%0,%1,%2,%3}, [%4];"
                 : "=r"(r[0]), "=r"(r[1]), "=r"(r[2]), "=r"(r[3]) : "r"(addr));
}
__device__ __forceinline__ void mma_fp16(float* c, const uint32_t* a, uint32_t b0, uint32_t b1) {
    asm volatile("mma.sync.aligned.m16n8k16.row.col.f32.f16.f16.f32 "
                 "{%0,%1,%2,%3}, {%4,%5,%6,%7}, {%8,%9}, {%0,%1,%2,%3};"
                 : "+f"(c[0]), "+f"(c[1]), "+f"(c[2]), "+f"(c[3])
                 : "r"(a[0]), "r"(a[1]), "r"(a[2]), "r"(a[3]), "r"(b0), "r"(b1));
}
__device__ __forceinline__ void mma_fp16_k8(float* c, uint32_t a0, uint32_t a1, uint32_t b0) {
    asm volatile("mma.sync.aligned.m16n8k8.row.col.f32.f16.f16.f32 "
                 "{%0,%1,%2,%3}, {%4,%5}, {%6}, {%0,%1,%2,%3};"
                 : "+f"(c[0]), "+f"(c[1]), "+f"(c[2]), "+f"(c[3])
                 : "r"(a0), "r"(a1), "r"(b0));
}
#define CP_ASYNC16(dst, src) \
    asm volatile("cp.async.cg.shared.global [%0], [%1], 16;" :: "r"(dst), "l"(src) : "memory")
#define CP_ASYNC_COMMIT() asm volatile("cp.async.commit_group;" ::: "memory")
#define CP_ASYNC_WAIT0()  asm volatile("cp.async.wait_group 0;" ::: "memory")

__device__ __forceinline__ uint32_t h2pack(float a, float b) {
    __half2 h = __floats2half2_rn(a, b);
    return *(uint32_t*)&h;
}
// pack two fp32 then relu in half2 (identical result to relu-then-pack)
__device__ __forceinline__ uint32_t h2pack_relu(float a, float b) {
    __half2 h = __hmax2(__floats2half2_rn(a, b), __float2half2_rn(0.0f));
    return *(uint32_t*)&h;
}
__device__ __forceinline__ uint32_t h2_addbias_relu(float a, float b, uint32_t b2p) {
    __half2 h = __hmax2(__hadd2(__floats2half2_rn(a, b), *(__half2*)&b2p),
                        __float2half2_rn(0.0f));
    return *(uint32_t*)&h;
}

__device__ __forceinline__ void compute_bias(int it, float4* sB4,
                                             const float* __restrict__ grid_q,
                                             const float* __restrict__ grid_kv, int tid) {
    const int jt = it & 3;
    const int i  = (it >> 2) & (ID - 1);
    const int b  = it >> 11;
    const int j  = jt * MROWS + tid;
    const float q0 = __ldg(grid_q + i * 3 + 0);
    const float q1 = __ldg(grid_q + i * 3 + 1);
    const float q2 = __ldg(grid_q + i * 3 + 2);
    const float p0 = q0 - grid_kv[(b * JD + j) * 3 + 0];
    const float p1 = q1 - grid_kv[(b * JD + j) * 3 + 1];
    const float p2 = q2 - grid_kv[(b * JD + j) * 3 + 2];
    sB4[tid] = make_float4(copysignf(__logf(1.0f + fabsf(p0)), p0),
                           copysignf(__logf(1.0f + fabsf(p1)), p1),
                           copysignf(__logf(1.0f + fabsf(p2)), p2), 1.0f);
}

// ---------------- main persistent kernel ----------------
__global__ __launch_bounds__(NTHREADS, 3)
void crpb_kernel(const float* __restrict__ grid_q,
                 const float* __restrict__ grid_kv,
                 const float* __restrict__ W1, const float* __restrict__ b1,
                 const float* __restrict__ b2,
                 const float* __restrict__ W3, const float* __restrict__ b3,
                 float* __restrict__ out)
{
    extern __shared__ __align__(1024) char smem[];
    uint32_t* sb2p  = (uint32_t*)(smem + OFF_B2H);   // 64 packed half2
    float*    sb3   = (float*)(smem + OFF_B3);
    float4*   sBias = (float4*)(smem + OFF_BIAS);    // 2 x 128

    const int tid  = threadIdx.x;
    const int lane = tid & 31;
    const int wid  = tid >> 5;
    const int g  = lane >> 2;
    const int t4 = lane & 3;

    // ---- one-time prologue ----
    if (tid < 64) {
        __half2 h = __floats2half2_rn(b2[2 * tid], b2[2 * tid + 1]);
        sb2p[tid] = *(uint32_t*)&h;
    }
    if (tid < DD) {
        // W3T image: 16 rows (o, rows 4..15 zero) x 128 cols (e), swizzled fp16
        const int e = tid;
        #pragma unroll
        for (int n = 0; n < 16; ++n) {
            unsigned byte = SWZ(n, e >> 3) + (unsigned)(e & 7) * 2u;
            float v = (n < 4) ? W3[e * 4 + n] : 0.0f;
            *(uint16_t*)(smem + OFF_W3T + byte) = __half_as_ushort(__float2half_rn(v));
        }
    }
    if (tid < 4) sb3[tid] = b3[tid];
    {
        uint32_t dst = smem_u32(smem + OFF_W2) + tid * 16;
        const char* src = (const char*)g_w2h + tid * 16;
        #pragma unroll
        for (int it = 0; it < 16; ++it) CP_ASYNC16(dst + it * 2048, src + it * 2048);
        CP_ASYNC_COMMIT();
    }

    // W1_aug B-fragments (k8), persistent: 16 regs
    uint32_t W1B[16];
    #pragma unroll
    for (int ng = 0; ng < 16; ++ng) {
        const int col = ng * 8 + g;
        float v0 = 0.0f, v1 = 0.0f;
        if (t4 == 0)      { v0 = W1[col];          v1 = W1[DD + col]; }
        else if (t4 == 1) { v0 = W1[2 * DD + col]; v1 = b1[col]; }
        W1B[ng] = h2pack(v0, v1);
    }

    const int nt = (NTILES - blockIdx.x + GRIDSZ - 1) / GRIDSZ;
    #define TILE_AT(k) (blockIdx.x + (k) * GRIDSZ)

    compute_bias(TILE_AT(0), sBias, grid_q, grid_kv, tid);
    CP_ASYNC_WAIT0();
    __syncthreads();

    const int brow_frag = (lane & 7) + ((lane >> 4) << 3);
    const unsigned bsel = (lane >> 3) & 1;
    const uint32_t w2b  = smem_u32(smem + OFF_W2);
    const uint32_t w3b  = smem_u32(smem + OFF_W3T);

    const float bias3_a = (t4 == 0) ? sb3[0] : sb3[2];   // col 2t4
    const float bias3_b = (t4 == 0) ? sb3[1] : sb3[3];   // col 2t4+1

    for (int k = 0; k < nt; ++k) {
        const float4* bcur = sBias + (k & 1) * 128;

        // bias A-fragments (k8 layout)
        uint32_t ab[2][2];
        {
            const float4 r0 = bcur[wid * 32 + g];
            const float4 r1 = bcur[wid * 32 + 8 + g];
            const float4 r2 = bcur[wid * 32 + 16 + g];
            const float4 r3 = bcur[wid * 32 + 24 + g];
            ab[0][0] = (t4 == 0) ? h2pack(r0.x, r0.y) : (t4 == 1) ? h2pack(r0.z, r0.w) : 0u;
            ab[0][1] = (t4 == 0) ? h2pack(r1.x, r1.y) : (t4 == 1) ? h2pack(r1.z, r1.w) : 0u;
            ab[1][0] = (t4 == 0) ? h2pack(r2.x, r2.y) : (t4 == 1) ? h2pack(r2.z, r2.w) : 0u;
            ab[1][1] = (t4 == 0) ? h2pack(r3.x, r3.y) : (t4 == 1) ? h2pack(r3.z, r3.w) : 0u;
        }
        __syncthreads();   // everyone has read bcur -> safe to overwrite other buffer
        if (k + 1 < nt)
            compute_bias(TILE_AT(k + 1), sBias + ((k + 1) & 1) * 128, grid_q, grid_kv, tid);

        // ---- L1 burst: 32 independent k8-MMAs -> all A fragments (64 regs) ----
        uint32_t A[2][8][4];
        #pragma unroll
        for (int mt = 0; mt < 2; ++mt)
            #pragma unroll
            for (int kc = 0; kc < 8; ++kc) {
                float cl[4] = {0, 0, 0, 0}, ch[4] = {0, 0, 0, 0};
                mma_fp16_k8(cl, ab[mt][0], ab[mt][1], W1B[2 * kc]);
                mma_fp16_k8(ch, ab[mt][0], ab[mt][1], W1B[2 * kc + 1]);
                A[mt][kc][0] = h2pack_relu(cl[0], cl[1]);
                A[mt][kc][1] = h2pack_relu(cl[2], cl[3]);
                A[mt][kc][2] = h2pack_relu(ch[0], ch[1]);
                A[mt][kc][3] = h2pack_relu(ch[2], ch[3]);
            }

        // ---- L2 (N-outer, K-inner) + L3 fold-by-MMA ----
        float ovC[2][4];
        #pragma unroll
        for (int mt = 0; mt < 2; ++mt)
            #pragma unroll
            for (int c = 0; c < 4; ++c) ovC[mt][c] = 0.0f;

        uint32_t Bf[2][4];
        ldsm_x4(Bf[0], w2b + SWZ(brow_frag, bsel));

        #pragma unroll
        for (int nb = 0; nb < 8; ++nb) {
            float acc[2][2][4];
            #pragma unroll
            for (int mt = 0; mt < 2; ++mt)
                #pragma unroll
                for (int n2 = 0; n2 < 2; ++n2)
                    #pragma unroll
                    for (int c = 0; c < 4; ++c) acc[mt][n2][c] = 0.0f;

            #pragma unroll
            for (int kc = 0; kc < 8; ++kc) {
                const int i = nb * 8 + kc;
                if (i < 63) {
                    const int nn = (i + 1) >> 3, kn = (i + 1) & 7;
                    ldsm_x4(Bf[(i + 1) & 1], w2b + SWZ(nn * 16 + brow_frag, kn * 2 + bsel));
                }
                const uint32_t* B = Bf[i & 1];
                mma_fp16(acc[0][0], A[0][kc], B[0], B[1]);
                mma_fp16(acc[0][1], A[0][kc], B[2], B[3]);
                mma_fp16(acc[1][0], A[1][kc], B[0], B[1]);
                mma_fp16(acc[1][1], A[1][kc], B[2], B[3]);
            }

            // L3 fold: pack -> +b2 -> relu (half2), then 1 MMA per mt vs W3T
            uint32_t W3f[4];
            ldsm_x4(W3f, w3b + SWZ(brow_frag, nb * 2 + bsel));
            const uint32_t b2a = sb2p[nb * 8 + t4];       // e0, e0+1
            const uint32_t b2b = sb2p[nb * 8 + 4 + t4];   // e0+8, e0+9
            #pragma unroll
            for (int mt = 0; mt < 2; ++mt) {
                uint32_t Ap[4];
                Ap[0] = h2_addbias_relu(acc[mt][0][0], acc[mt][0][1], b2a);
                Ap[1] = h2_addbias_relu(acc[mt][0][2], acc[mt][0][3], b2a);
                Ap[2] = h2_addbias_relu(acc[mt][1][0], acc[mt][1][1], b2b);
                Ap[3] = h2_addbias_relu(acc[mt][1][2], acc[mt][1][3], b2b);
                mma_fp16(ovC[mt], Ap, W3f[0], W3f[1]);
            }
        }

        // ---- direct store: lanes t4<2 hold cols {2t4, 2t4+1} = outputs o ----
        if (t4 < 2) {
            const int it = TILE_AT(k);
            const int jt = it & 3;
            const int i  = (it >> 2) & (ID - 1);
            const int b  = it >> 11;
            const long os   = (long)ID * JD;
            const long rowb = ((long)(b * 4) * ID + i) * JD + jt * MROWS + wid * 32 + g;
            const long oa   = (long)(2 * t4) * os;       // output plane 2t4
            const long ob   = oa + os;                   // output plane 2t4+1
            #pragma unroll
            for (int mt = 0; mt < 2; ++mt) {
                const long r0 = rowb + mt * 16;
                out[r0 + oa]      = ovC[mt][0] + bias3_a;
                out[r0 + ob]      = ovC[mt][1] + bias3_b;
                out[r0 + 8 + oa]  = ovC[mt][2] + bias3_a;
                out[r0 + 8 + ob]  = ovC[mt][3] + bias3_b;
            }
        }
    }
}

extern "C" void kernel_launch(void* const* d_in, const int* in_sizes, int n_in,
                              void* d_out, int out_size)
{
    const float* grid_q  = (const float*)d_in[0];
    const float* grid_kv = (const float*)d_in[1];
    const float* W1      = (const float*)d_in[2];
    const float* b1      = (const float*)d_in[3];
    const float* W2      = (const float*)d_in[4];
    const float* b2      = (const float*)d_in[5];
    const float* W3      = (const float*)d_in[6];
    const float* b3      = (const float*)d_in[7];
    float* out = (float*)d_out;

    prep_w2<<<DD * DD / 256, 256>>>(W2);

    cudaFuncSetAttribute(crpb_kernel,
                         cudaFuncAttributeMaxDynamicSharedMemorySize, SMEM_BYTES);
    crpb_kernel<<<GRIDSZ, NTHREADS, SMEM_BYTES>>>(
        grid_q, grid_kv, W1, b1, b2, W3, b3, out);
}